// round 5
// baseline (speedup 1.0000x reference)
#include <cuda_runtime.h>

#define NB 16
#define CI 4
#define CO 32
#define HH 400
#define RK 4
#define H4 100          // HH/4
#define KT 80           // k-tile in rowcol kernel
#define KT4 20          // KT/4

// ---- scratch (static device arrays: allocation-free) ----
__device__ float g_xt[NB*CI*HH*HH];     // X transposed per (n,c): [n][c][j][k]
__device__ float g_rows[NB*CO*HH];      // rows[n][o][i]
__device__ float g_cols[NB*CO*HH];      // cols[n][o][j]
__device__ float g_lt[HH*CO*CI*RK];     // weight re-layout: [j][o][c][r]

// ============================================================
// Kernel 0a: 32x32 tiled transpose of each (n,c) 400x400 image
// ============================================================
__global__ void transpose_k(const float* __restrict__ x) {
    __shared__ float tile[32][33];
    int nc = blockIdx.z;
    int k0 = blockIdx.x * 32, j0 = blockIdx.y * 32;
    const float* src = x    + nc * (HH*HH);
    float*       dst = g_xt + nc * (HH*HH);
    int tx = threadIdx.x, ty = threadIdx.y;
    #pragma unroll
    for (int dy = 0; dy < 32; dy += 8) {
        int k = k0 + ty + dy, j = j0 + tx;
        if (k < HH && j < HH) tile[ty+dy][tx] = src[k*HH + j];
    }
    __syncthreads();
    #pragma unroll
    for (int dy = 0; dy < 32; dy += 8) {
        int j = j0 + ty + dy, k = k0 + tx;
        if (j < HH && k < HH) dst[j*HH + k] = tile[tx][ty+dy];
    }
}

// ============================================================
// Kernel 0b: weight re-layout  L[o,c,j,r] -> LT[j][o][c][r]
// (gives each main-kernel thread 64B-contiguous Lj reads)
// ============================================================
__global__ void build_lt_k(const float* __restrict__ wl) {
    int idx = blockIdx.x * blockDim.x + threadIdx.x;
    if (idx >= CO*CI*HH*RK) return;
    int r = idx & 3;
    int t = idx >> 2;
    int j = t % HH; t /= HH;
    int c = t & 3;
    int o = t >> 2;
    g_lt[j*(CO*CI*RK) + o*(CI*RK) + c*RK + r] = wl[idx];
}

// ============================================================
// Kernel 1: rows & cols.
//   blockIdx.x = i (or j), blockIdx.y: 0 = rows (from X), 1 = cols (from XT)
//   dst[n,o,i] = sum_c sum_k src[n,c,i,k] * ( sum_r L[o,c,i,r]*L[o,c,k,r] )
//   Per (c, k-tile): build T-slice Ts[o][k] in smem once, then all 16 n
//   contract against it. 256 threads: lane=o, and (nq:2 x kh:4) groups.
// ============================================================
__global__ void __launch_bounds__(256) rowcol_k(const float* __restrict__ x,
                                                const float* __restrict__ wl) {
    int i = blockIdx.x;
    const float* xsrc = blockIdx.y ? g_xt  : x;
    float*       dst  = blockIdx.y ? g_cols : g_rows;

    __shared__ float4 Lis4[CI][CO];       // L[o,c,i,:]
    __shared__ float4 xs4[NB][KT4];       // x[n,c,i, ktile]  (per stage)
    __shared__ float  Ts[CO][84];         // T-slice, pad 84 -> conflict-free LDS.128
    __shared__ float  red[4][CO][NB];

    int t = threadIdx.x;
    if (t < CO*CI) {
        int o = t >> 2, c = t & 3;
        Lis4[c][o] = *(const float4*)&wl[((o*CI + c)*HH + i)*RK];
    }

    int o  = t & 31;
    int g  = t >> 5;       // 0..7
    int nq = g & 1;        // n base = nq*8
    int kh = g >> 1;       // k quarter (20 k = 5 float4)

    float acc[8];
    #pragma unroll
    for (int u = 0; u < 8; u++) acc[u] = 0.f;

    for (int c = 0; c < CI; c++) {
        for (int kt = 0; kt < HH/KT; kt++) {
            __syncthreads();   // protect xs4/Ts from previous stage's readers
            // stage x tile: 16 x 20 float4 (coalesced)
            for (int u = t; u < NB*KT4; u += 256) {
                int n = u / KT4, q = u - n*KT4;
                xs4[n][q] = *(const float4*)&xsrc[((n*CI + c)*HH + i)*HH + kt*KT + q*4];
            }
            // build Ts[o][k] = dot(L[o,c,i,:], L[o,c,k,:])  (2560 entries)
            #pragma unroll
            for (int u = 0; u < 10; u++) {
                int e  = t + u*256;
                int oo = e / KT, kk = e - oo*KT;
                float4 lv = *(const float4*)&wl[((oo*CI + c)*HH + kt*KT + kk)*RK];
                float4 li = Lis4[c][oo];
                Ts[oo][kk] = lv.x*li.x + lv.y*li.y + lv.z*li.z + lv.w*li.w;
            }
            __syncthreads();
            // contract: acc[n] += sum_k xs[n][k] * Ts[o][k]
            const float4* tsr = (const float4*)&Ts[o][0];   // o*84 floats: 16B aligned
            #pragma unroll
            for (int q = 0; q < 5; q++) {
                float4 tv = tsr[kh*5 + q];
                #pragma unroll
                for (int nn = 0; nn < 8; nn++) {
                    float4 xv = xs4[nq*8 + nn][kh*5 + q];
                    acc[nn] += xv.x*tv.x + xv.y*tv.y + xv.z*tv.z + xv.w*tv.w;
                }
            }
        }
    }
    // reduce over kh quarters
    #pragma unroll
    for (int nn = 0; nn < 8; nn++) red[kh][o][nq*8 + nn] = acc[nn];
    __syncthreads();
    for (int u = t; u < CO*NB; u += 256) {
        int o2 = u & 31, n2 = u >> 5;
        dst[(n2*CO + o2)*HH + i] =
            red[0][o2][n2] + red[1][o2][n2] + red[2][o2][n2] + red[3][o2][n2];
    }
}

// ============================================================
// Kernel 2: main elementwise kernel.
//   block = i. 800 threads: jg = t%100 (j-group of 4), og = t/100 -> 4 o's.
//   o's processed in 2 passes of 2 to keep the G register tile at 32 floats
//   (no local spills). x-row for all (n,c) staged in dyn smem.
//   out[n,o,i,j] = rows[n,o,i]+bias[o] + cols[n,o,j] - sum_c x[n,c,i,j]*G[o,c]
// ============================================================
__global__ void __launch_bounds__(800, 1) main_k(const float* __restrict__ x,
                                                 const float* __restrict__ wl,
                                                 const float* __restrict__ bias,
                                                 float* __restrict__ out) {
    extern __shared__ float4 sx4[];           // [NB*CI*H4] = 6400 float4 = 100 KB
    __shared__ float  rbs[NB*CO];             // rows + bias
    __shared__ float4 sLi[CO*CI];             // L[o,c,i,:]

    int t = threadIdx.x;
    int i = blockIdx.x;

    for (int u = t; u < NB*CI*H4; u += 800) {
        int n   = u / (CI*H4);
        int rem = u - n*(CI*H4);
        int c   = rem / H4;
        int q   = rem - c*H4;
        sx4[u] = *(const float4*)&x[((n*CI + c)*HH + i)*HH + q*4];
    }
    if (t < NB*CO) {
        int n = t >> 5, o = t & 31;
        rbs[t] = g_rows[(n*CO + o)*HH + i] + bias[o];
    }
    if (t < CO*CI) {
        int o = t >> 2, c = t & 3;
        sLi[t] = *(const float4*)&wl[((o*CI + c)*HH + i)*RK];
    }
    __syncthreads();

    int og = t / 100;          // 0..7  (4 o's each)
    int jg = t - og * 100;     // 0..99

    #pragma unroll
    for (int op = 0; op < 2; op++) {
        // G[oo2][c][jj] = dot(L[o,c,i,:], L[o,c,j,:]) for this o-pair
        float G[2][4][4];
        #pragma unroll
        for (int oo2 = 0; oo2 < 2; oo2++) {
            int o = og*4 + op*2 + oo2;
            #pragma unroll
            for (int c = 0; c < 4; c++) {
                float4 li = sLi[o*4 + c];
                #pragma unroll
                for (int jj = 0; jj < 4; jj++) {
                    float4 lj = *(const float4*)&g_lt[(jg*4 + jj)*(CO*CI*RK) + o*(CI*RK) + c*RK];
                    G[oo2][c][jj] = li.x*lj.x + li.y*lj.y + li.z*lj.z + li.w*lj.w;
                }
            }
        }
        for (int n = 0; n < NB; n++) {
            float4 xv0 = sx4[(n*CI + 0)*H4 + jg];
            float4 xv1 = sx4[(n*CI + 1)*H4 + jg];
            float4 xv2 = sx4[(n*CI + 2)*H4 + jg];
            float4 xv3 = sx4[(n*CI + 3)*H4 + jg];
            #pragma unroll
            for (int oo2 = 0; oo2 < 2; oo2++) {
                int o = og*4 + op*2 + oo2;
                float4 cv = *(const float4*)&g_cols[(n*CO + o)*HH + jg*4];
                float rb = rbs[n*CO + o];
                float4 res;
                res.x = rb + cv.x - (xv0.x*G[oo2][0][0] + xv1.x*G[oo2][1][0] + xv2.x*G[oo2][2][0] + xv3.x*G[oo2][3][0]);
                res.y = rb + cv.y - (xv0.y*G[oo2][0][1] + xv1.y*G[oo2][1][1] + xv2.y*G[oo2][2][1] + xv3.y*G[oo2][3][1]);
                res.z = rb + cv.z - (xv0.z*G[oo2][0][2] + xv1.z*G[oo2][1][2] + xv2.z*G[oo2][2][2] + xv3.z*G[oo2][3][2]);
                res.w = rb + cv.w - (xv0.w*G[oo2][0][3] + xv1.w*G[oo2][1][3] + xv2.w*G[oo2][2][3] + xv3.w*G[oo2][3][3]);
                *(float4*)&out[((n*CO + o)*HH + i)*HH + jg*4] = res;
            }
        }
    }
}

// ============================================================
extern "C" void kernel_launch(void* const* d_in, const int* in_sizes, int n_in,
                              void* d_out, int out_size) {
    // defensive input mapping by element count
    const float* x    = (const float*)d_in[0];
    const float* wl   = (const float*)d_in[1];
    const float* bias = (const float*)d_in[2];
    for (int k = 0; k < n_in; k++) {
        if (in_sizes[k] == NB*CI*HH*HH) x    = (const float*)d_in[k];
        else if (in_sizes[k] == CO*CI*HH*RK) wl = (const float*)d_in[k];
        else if (in_sizes[k] == CO)      bias = (const float*)d_in[k];
    }
    float* out = (float*)d_out;

    cudaFuncSetAttribute(main_k, cudaFuncAttributeMaxDynamicSharedMemorySize,
                         NB*CI*H4*(int)sizeof(float4));

    transpose_k<<<dim3((HH+31)/32, (HH+31)/32, NB*CI), dim3(32, 8)>>>(x);
    build_lt_k<<<(CO*CI*HH*RK + 255)/256, 256>>>(wl);
    rowcol_k<<<dim3(HH, 2), 256>>>(x, wl);
    main_k<<<HH, 800, NB*CI*H4*sizeof(float4)>>>(x, wl, bias, out);
}

// round 6
// speedup vs baseline: 1.0611x; 1.0611x over previous
#include <cuda_runtime.h>

#define NB 16
#define CI 4
#define CO 32
#define HH 400
#define RK 4
#define H4 100          // HH/4
#define KT 80           // k-tile in rowcol kernel
#define KT4 20          // KT/4

// ---- scratch (static device arrays: allocation-free) ----
__device__ float g_xt[NB*CI*HH*HH];     // X transposed per (n,c): [n][c][j][k]
__device__ float g_rows[NB*CO*HH];      // rows[n][o][i]
__device__ float g_cols[NB*CO*HH];      // cols[n][o][j]
__device__ float g_lt[HH*CO*CI*RK];     // weight re-layout: [j][o][c][r]

// ============================================================
// Kernel 0a: 32x32 tiled transpose of each (n,c) 400x400 image
// ============================================================
__global__ void transpose_k(const float* __restrict__ x) {
    __shared__ float tile[32][33];
    int nc = blockIdx.z;
    int k0 = blockIdx.x * 32, j0 = blockIdx.y * 32;
    const float* src = x    + nc * (HH*HH);
    float*       dst = g_xt + nc * (HH*HH);
    int tx = threadIdx.x, ty = threadIdx.y;
    #pragma unroll
    for (int dy = 0; dy < 32; dy += 8) {
        int k = k0 + ty + dy, j = j0 + tx;
        if (k < HH && j < HH) tile[ty+dy][tx] = src[k*HH + j];
    }
    __syncthreads();
    #pragma unroll
    for (int dy = 0; dy < 32; dy += 8) {
        int j = j0 + ty + dy, k = k0 + tx;
        if (j < HH && k < HH) dst[j*HH + k] = tile[tx][ty+dy];
    }
}

// ============================================================
// Kernel 0b: weight re-layout  L[o,c,j,r] -> LT[j][o][c][r]
// ============================================================
__global__ void build_lt_k(const float* __restrict__ wl) {
    int idx = blockIdx.x * blockDim.x + threadIdx.x;
    if (idx >= CO*CI*HH*RK) return;
    int r = idx & 3;
    int t = idx >> 2;
    int j = t % HH; t /= HH;
    int c = t & 3;
    int o = t >> 2;
    g_lt[j*(CO*CI*RK) + o*(CI*RK) + c*RK + r] = wl[idx];
}

// ============================================================
// Kernel 1: rows & cols.
//   Ts stored TRANSPOSED: Ts2[k][o] (pad CO+1) so the contract's
//   per-lane (lane = o) loads are consecutive-address, conflict-free.
// ============================================================
__global__ void __launch_bounds__(256) rowcol_k(const float* __restrict__ x,
                                                const float* __restrict__ wl) {
    int i = blockIdx.x;
    const float* xsrc = blockIdx.y ? g_xt  : x;
    float*       dst  = blockIdx.y ? g_cols : g_rows;

    __shared__ float4 Lis4[CI][CO];       // L[o,c,i,:]
    __shared__ float4 xs4[NB][KT4];       // x[n,c,i, ktile]
    __shared__ float  Ts2[KT][CO+1];      // T-slice transposed: [k][o]
    __shared__ float  red[4][CO][NB];

    int t = threadIdx.x;
    if (t < CO*CI) {
        int o = t >> 2, c = t & 3;
        Lis4[c][o] = *(const float4*)&wl[((o*CI + c)*HH + i)*RK];
    }

    int o  = t & 31;
    int g  = t >> 5;       // 0..7
    int nq = g & 1;        // n base = nq*8
    int kh = g >> 1;       // k quarter (20 k = 5 float4)

    float acc[8];
    #pragma unroll
    for (int u = 0; u < 8; u++) acc[u] = 0.f;

    for (int c = 0; c < CI; c++) {
        for (int kt = 0; kt < HH/KT; kt++) {
            __syncthreads();   // protect xs4/Ts2 from previous stage's readers
            // stage x tile: 16 x 20 float4 (coalesced)
            for (int u = t; u < NB*KT4; u += 256) {
                int n = u / KT4, q = u - n*KT4;
                xs4[n][q] = *(const float4*)&xsrc[((n*CI + c)*HH + i)*HH + kt*KT + q*4];
            }
            // build Ts2[k][o] = dot(L[o,c,i,:], L[o,c,k,:])  (2560 entries)
            #pragma unroll
            for (int u = 0; u < 10; u++) {
                int e  = t + u*256;
                int oo = e / KT, kk = e - oo*KT;
                float4 lv = *(const float4*)&wl[((oo*CI + c)*HH + kt*KT + kk)*RK];
                float4 li = Lis4[c][oo];
                Ts2[kk][oo] = lv.x*li.x + lv.y*li.y + lv.z*li.z + lv.w*li.w;
            }
            __syncthreads();
            // contract: acc[n] += sum_k xs[n][k] * Ts2[k][o]
            #pragma unroll
            for (int q = 0; q < 5; q++) {
                int k4 = (kh*5 + q) * 4;
                float t0 = Ts2[k4+0][o];
                float t1 = Ts2[k4+1][o];
                float t2 = Ts2[k4+2][o];
                float t3 = Ts2[k4+3][o];
                #pragma unroll
                for (int nn = 0; nn < 8; nn++) {
                    float4 xv = xs4[nq*8 + nn][kh*5 + q];   // broadcast across lanes
                    acc[nn] += xv.x*t0 + xv.y*t1 + xv.z*t2 + xv.w*t3;
                }
            }
        }
    }
    // reduce over kh quarters
    #pragma unroll
    for (int nn = 0; nn < 8; nn++) red[kh][o][nq*8 + nn] = acc[nn];
    __syncthreads();
    for (int u = t; u < CO*NB; u += 256) {
        int o2 = u & 31, n2 = u >> 5;
        dst[(n2*CO + o2)*HH + i] =
            red[0][o2][n2] + red[1][o2][n2] + red[2][o2][n2] + red[3][o2][n2];
    }
}

// ============================================================
// Kernel 2: main elementwise kernel.
//   grid (HH, 2): block = (i, o-half of 16). 800 threads:
//   jg = t%100 (j-group of 4), og = t/100 -> 2 o's each, SINGLE pass
//   (no xv re-reads). cols loads register-double-buffered across the
//   n-loop so the ~250-cyc L2 latency is overlapped (MLP 2).
//   out[n,o,i,j] = rows[n,o,i]+bias[o] + cols[n,o,j] - sum_c x[n,c,i,j]*G[o,c,j]
// ============================================================
__global__ void __launch_bounds__(800, 1) main_k(const float* __restrict__ x,
                                                 const float* __restrict__ wl,
                                                 const float* __restrict__ bias,
                                                 float* __restrict__ out) {
    extern __shared__ float4 sx4[];           // [NB*CI*H4] = 6400 float4 = 100 KB
    __shared__ float  rbs[NB*16];             // rows + bias for this block's 16 o's
    __shared__ float4 sLi[16*CI];             // L[o,c,i,:] for this block's 16 o's

    int t = threadIdx.x;
    int i = blockIdx.x;
    int obase = blockIdx.y * 16;

    for (int u = t; u < NB*CI*H4; u += 800) {
        int n   = u / (CI*H4);
        int rem = u - n*(CI*H4);
        int c   = rem / H4;
        int q   = rem - c*H4;
        sx4[u] = *(const float4*)&x[((n*CI + c)*HH + i)*HH + q*4];
    }
    if (t < NB*16) {
        int n = t >> 4, oL = t & 15;
        rbs[t] = g_rows[(n*CO + obase + oL)*HH + i] + bias[obase + oL];
    }
    if (t < 16*CI) {
        int oL = t >> 2, c = t & 3;
        sLi[t] = *(const float4*)&wl[(((obase + oL)*CI + c)*HH + i)*RK];
    }
    __syncthreads();

    int og = t / 100;          // 0..7 -> 2 o's each
    int jg = t - og * 100;     // 0..99
    int oL0 = og * 2;
    int o0  = obase + oL0;

    // G4[oo][c] = { dot(L[o,c,i,:], L[o,c,jg*4+jj,:]) : jj=0..3 }
    float4 G4[2][4];
    #pragma unroll
    for (int oo = 0; oo < 2; oo++) {
        int oL = oL0 + oo;
        #pragma unroll
        for (int c = 0; c < 4; c++) {
            float4 li = sLi[oL*4 + c];
            const float* ltb = &g_lt[(size_t)(jg*4)*(CO*CI*RK) + (obase + oL)*(CI*RK) + c*RK];
            float4 l0 = *(const float4*)(ltb + 0*(CO*CI*RK));
            float4 l1 = *(const float4*)(ltb + 1*(CO*CI*RK));
            float4 l2 = *(const float4*)(ltb + 2*(CO*CI*RK));
            float4 l3 = *(const float4*)(ltb + 3*(CO*CI*RK));
            G4[oo][c].x = li.x*l0.x + li.y*l0.y + li.z*l0.z + li.w*l0.w;
            G4[oo][c].y = li.x*l1.x + li.y*l1.y + li.z*l1.z + li.w*l1.w;
            G4[oo][c].z = li.x*l2.x + li.y*l2.y + li.z*l2.z + li.w*l2.w;
            G4[oo][c].w = li.x*l3.x + li.y*l3.y + li.z*l3.z + li.w*l3.w;
        }
    }

    // cols pointers for the two o's of this thread
    const float* cp0 = &g_cols[(size_t)(0*CO + o0    )*HH + jg*4];
    const float* cp1 = &g_cols[(size_t)(0*CO + o0 + 1)*HH + jg*4];

    // prefetch n=0
    float4 cva0 = *(const float4*)cp0;
    float4 cva1 = *(const float4*)cp1;

    for (int n = 0; n < NB; n++) {
        // prefetch next n's cols (clamped at the end; redundant load is harmless)
        int np = (n < NB-1) ? n+1 : n;
        float4 cvb0 = *(const float4*)(cp0 + (size_t)np*CO*HH);
        float4 cvb1 = *(const float4*)(cp1 + (size_t)np*CO*HH);

        float4 xv0 = sx4[(n*CI + 0)*H4 + jg];
        float4 xv1 = sx4[(n*CI + 1)*H4 + jg];
        float4 xv2 = sx4[(n*CI + 2)*H4 + jg];
        float4 xv3 = sx4[(n*CI + 3)*H4 + jg];

        #pragma unroll
        for (int oo = 0; oo < 2; oo++) {
            float4 cv = oo ? cva1 : cva0;
            float rb  = rbs[n*16 + oL0 + oo];
            float4 res;
            res.x = rb + cv.x - (xv0.x*G4[oo][0].x + xv1.x*G4[oo][1].x + xv2.x*G4[oo][2].x + xv3.x*G4[oo][3].x);
            res.y = rb + cv.y - (xv0.y*G4[oo][0].y + xv1.y*G4[oo][1].y + xv2.y*G4[oo][2].y + xv3.y*G4[oo][3].y);
            res.z = rb + cv.z - (xv0.z*G4[oo][0].z + xv1.z*G4[oo][1].z + xv2.z*G4[oo][2].z + xv3.z*G4[oo][3].z);
            res.w = rb + cv.w - (xv0.w*G4[oo][0].w + xv1.w*G4[oo][1].w + xv2.w*G4[oo][2].w + xv3.w*G4[oo][3].w);
            *(float4*)&out[((size_t)(n*CO + o0 + oo)*HH + i)*HH + jg*4] = res;
        }
        cva0 = cvb0;
        cva1 = cvb1;
    }
}

// ============================================================
extern "C" void kernel_launch(void* const* d_in, const int* in_sizes, int n_in,
                              void* d_out, int out_size) {
    // defensive input mapping by element count
    const float* x    = (const float*)d_in[0];
    const float* wl   = (const float*)d_in[1];
    const float* bias = (const float*)d_in[2];
    for (int k = 0; k < n_in; k++) {
        if (in_sizes[k] == NB*CI*HH*HH) x    = (const float*)d_in[k];
        else if (in_sizes[k] == CO*CI*HH*RK) wl = (const float*)d_in[k];
        else if (in_sizes[k] == CO)      bias = (const float*)d_in[k];
    }
    float* out = (float*)d_out;

    cudaFuncSetAttribute(main_k, cudaFuncAttributeMaxDynamicSharedMemorySize,
                         NB*CI*H4*(int)sizeof(float4));

    transpose_k<<<dim3((HH+31)/32, (HH+31)/32, NB*CI), dim3(32, 8)>>>(x);
    build_lt_k<<<(CO*CI*HH*RK + 255)/256, 256>>>(wl);
    rowcol_k<<<dim3(HH, 2), 256>>>(x, wl);
    main_k<<<dim3(HH, 2), 800, NB*CI*H4*sizeof(float4)>>>(x, wl, bias, out);
}